// round 1
// baseline (speedup 1.0000x reference)
#include <cuda_runtime.h>

#define MAXN 50000
#define MAXE 800000
#define MAXET (MAXN + MAXE)

// ---------------- scratch (device globals; no allocation allowed) ----------
__device__ float g_xl[MAXN * 128];     // source transform  [N,128]
__device__ float g_xr[MAXN * 128];     // target transform  [N,128]
__device__ float g_h [MAXN * 128];     // layer output accumulator / next act
__device__ float g_p [MAXET * 8];      // per-edge scores -> probs [Etot,H]
__device__ float g_m [MAXN * 8];       // segment max  [N,H]
__device__ float g_d [MAXN * 8];       // segment sum  [N,H]

// ---------------- helpers --------------------------------------------------
__device__ __forceinline__ void atomicMaxF(float* addr, float v) {
    // monotone float max via int atomics (valid for mixed signs, init = -inf)
    if (v >= 0.0f) atomicMax((int*)addr, __float_as_int(v));
    else           atomicMin((unsigned int*)addr, __float_as_uint(v));
}

// ---------------- GEMM: C[n,128] = A[n,128] @ W[128,128] -------------------
// block: 256 threads, tile 32 rows x 128 cols, 4x4 register tile per thread
__global__ void gemm128(const float* __restrict__ Aext,
                        const float* __restrict__ W,
                        int useH, int dstSel, int n) {
    __shared__ float As[32][33];     // [row][k], padded
    __shared__ float Ws[32][128];    // [k][col]
    const float* A = useH ? g_h : Aext;
    float* C = (dstSel == 0) ? g_xl : ((dstSel == 1) ? g_xr : g_h);

    int tid  = threadIdx.x;
    int row0 = blockIdx.x * 32;
    int cg   = tid & 31;     // col group: cols [4cg, 4cg+4)
    int rg   = tid >> 5;     // row group: rows [4rg, 4rg+4)

    float acc[4][4] = {};

    for (int kk = 0; kk < 128; kk += 32) {
        // load A tile 32 rows x 32 k
        {
            int r  = tid >> 3;          // 0..31
            int k4 = (tid & 7) * 4;     // 0..28
            float4 v = make_float4(0.f, 0.f, 0.f, 0.f);
            if (row0 + r < n)
                v = *(const float4*)&A[(size_t)(row0 + r) * 128 + kk + k4];
            As[r][k4 + 0] = v.x; As[r][k4 + 1] = v.y;
            As[r][k4 + 2] = v.z; As[r][k4 + 3] = v.w;
        }
        // load W tile 32 k x 128 cols
        #pragma unroll
        for (int t = 0; t < 4; ++t) {
            int f = tid + t * 256;      // float4 id, 1024 total
            int k = f >> 5;
            int c = (f & 31) * 4;
            *(float4*)&Ws[k][c] = *(const float4*)&W[(size_t)(kk + k) * 128 + c];
        }
        __syncthreads();

        #pragma unroll
        for (int k = 0; k < 32; ++k) {
            float a0 = As[rg * 4 + 0][k];
            float a1 = As[rg * 4 + 1][k];
            float a2 = As[rg * 4 + 2][k];
            float a3 = As[rg * 4 + 3][k];
            float4 w = *(const float4*)&Ws[k][cg * 4];
            acc[0][0] += a0 * w.x; acc[0][1] += a0 * w.y; acc[0][2] += a0 * w.z; acc[0][3] += a0 * w.w;
            acc[1][0] += a1 * w.x; acc[1][1] += a1 * w.y; acc[1][2] += a1 * w.z; acc[1][3] += a1 * w.w;
            acc[2][0] += a2 * w.x; acc[2][1] += a2 * w.y; acc[2][2] += a2 * w.z; acc[2][3] += a2 * w.w;
            acc[3][0] += a3 * w.x; acc[3][1] += a3 * w.y; acc[3][2] += a3 * w.z; acc[3][3] += a3 * w.w;
        }
        __syncthreads();
    }

    #pragma unroll
    for (int i = 0; i < 4; ++i) {
        int r = row0 + rg * 4 + i;
        if (r < n)
            *(float4*)&C[(size_t)r * 128 + cg * 4] =
                make_float4(acc[i][0], acc[i][1], acc[i][2], acc[i][3]);
    }
}

// ---------------- per-layer init: h=0, m=-inf, d=0 -------------------------
__global__ void init_layer(int n) {
    int i = blockIdx.x * blockDim.x + threadIdx.x;
    if (i < n * 128) g_h[i] = 0.0f;
    if (i < n * 8) {
        g_m[i] = __int_as_float(0xFF800000);   // -inf
        g_d[i] = 0.0f;
    }
}

// ---------------- edge score: warp per edge --------------------------------
// score[e,h] = sum_c att[h,c] * leaky_relu(xl[src,h,c] + xr[dst,h,c], 0.2)
__global__ void edge_score(const int* __restrict__ ei,
                           const float* __restrict__ att,
                           int E, int etot) {
    int e = blockIdx.x * 8 + (threadIdx.x >> 5);
    if (e >= etot) return;
    int lane = threadIdx.x & 31;
    int s, d;
    if (e < E) { s = __ldg(&ei[e]); d = __ldg(&ei[E + e]); }
    else       { s = e - E; d = s; }

    float4 a4 = *(const float4*)&att[lane * 4];
    float4 l4 = *(const float4*)&g_xl[(size_t)s * 128 + lane * 4];
    float4 r4 = *(const float4*)&g_xr[(size_t)d * 128 + lane * 4];

    float v0 = l4.x + r4.x; v0 = v0 > 0.f ? v0 : 0.2f * v0;
    float v1 = l4.y + r4.y; v1 = v1 > 0.f ? v1 : 0.2f * v1;
    float v2 = l4.z + r4.z; v2 = v2 > 0.f ? v2 : 0.2f * v2;
    float v3 = l4.w + r4.w; v3 = v3 > 0.f ? v3 : 0.2f * v3;

    float part = v0 * a4.x + v1 * a4.y + v2 * a4.z + v3 * a4.w;
    part += __shfl_xor_sync(0xffffffffu, part, 1);
    part += __shfl_xor_sync(0xffffffffu, part, 2);

    if ((lane & 3) == 0) {
        int h = lane >> 2;
        g_p[(size_t)e * 8 + h] = part;
        atomicMaxF(&g_m[(size_t)d * 8 + h], part);
    }
}

// ---------------- softmax normalize: thread per (edge,head) ----------------
__global__ void edge_norm(const int* __restrict__ ei, int E, int etot) {
    int idx = blockIdx.x * blockDim.x + threadIdx.x;
    if (idx >= etot * 8) return;
    int e = idx >> 3;
    int h = idx & 7;
    int d = (e < E) ? __ldg(&ei[E + e]) : (e - E);
    float sc = g_p[idx];
    float p  = __expf(sc - g_m[(size_t)d * 8 + h]);
    g_p[idx] = p;
    atomicAdd(&g_d[(size_t)d * 8 + h], p);
}

// ---------------- aggregation: warp per edge, float4 atomics ---------------
__global__ void edge_aggr(const int* __restrict__ ei, int E, int etot) {
    int e = blockIdx.x * 8 + (threadIdx.x >> 5);
    if (e >= etot) return;
    int lane = threadIdx.x & 31;
    int s, d;
    if (e < E) { s = __ldg(&ei[e]); d = __ldg(&ei[E + e]); }
    else       { s = e - E; d = s; }
    int h = lane >> 2;
    float alpha = g_p[(size_t)e * 8 + h] / (g_d[(size_t)d * 8 + h] + 1e-16f);
    float4 l4 = *(const float4*)&g_xl[(size_t)s * 128 + lane * 4];
    float4 v  = make_float4(alpha * l4.x, alpha * l4.y, alpha * l4.z, alpha * l4.w);
    atomicAdd((float4*)&g_h[(size_t)d * 128 + lane * 4], v);
}

// ---------------- bias + relu (in place on g_h) ----------------------------
__global__ void bias_relu(const float* __restrict__ b, int n) {
    int i = blockIdx.x * blockDim.x + threadIdx.x;
    if (i >= n * 128) return;
    float v = g_h[i] + b[i & 127];
    g_h[i] = v > 0.f ? v : 0.f;
}

// ---------------- final fc: out[n,10] = g_h[n,128] @ Wfc + bfc -------------
__global__ void fc_out(const float* __restrict__ Wfc,
                       const float* __restrict__ bfc,
                       float* __restrict__ out, int n) {
    __shared__ float Ws[128 * 10];
    __shared__ float bs[10];
    for (int i = threadIdx.x; i < 1280; i += blockDim.x) Ws[i] = Wfc[i];
    if (threadIdx.x < 10) bs[threadIdx.x] = bfc[threadIdx.x];
    __syncthreads();
    int idx = blockIdx.x * blockDim.x + threadIdx.x;
    if (idx >= n * 10) return;
    int node = idx / 10;
    int c    = idx % 10;
    const float* hrow = &g_h[(size_t)node * 128];
    float acc = bs[c];
    #pragma unroll
    for (int k = 0; k < 128; ++k) acc += hrow[k] * Ws[k * 10 + c];
    out[idx] = acc;
}

// ---------------- launch ---------------------------------------------------
extern "C" void kernel_launch(void* const* d_in, const int* in_sizes, int n_in,
                              void* d_out, int out_size) {
    const float* x    = (const float*)d_in[0];
    const int*   ei   = (const int*)  d_in[1];
    const float* Wl1  = (const float*)d_in[2];
    const float* Wr1  = (const float*)d_in[3];
    const float* att1 = (const float*)d_in[4];
    const float* b1   = (const float*)d_in[5];
    const float* Wl2  = (const float*)d_in[6];
    const float* Wr2  = (const float*)d_in[7];
    const float* att2 = (const float*)d_in[8];
    const float* b2   = (const float*)d_in[9];
    const float* Wfc  = (const float*)d_in[10];
    const float* bfc  = (const float*)d_in[11];
    float* out = (float*)d_out;

    int n    = in_sizes[0] / 128;
    int E    = in_sizes[1] / 2;
    int etot = E + n;

    int gemm_blocks = (n + 31) / 32;
    int ew_blocks   = (etot + 7) / 8;            // warp-per-edge kernels
    int node_blocks = (n * 128 + 255) / 256;
    int nh_blocks   = (etot * 8 + 255) / 256;
    int fc_blocks   = (n * 10 + 255) / 256;

    // ---- layer 1 ----
    gemm128<<<gemm_blocks, 256>>>(x, Wl1, 0, 0, n);    // -> g_xl
    gemm128<<<gemm_blocks, 256>>>(x, Wr1, 0, 1, n);    // -> g_xr
    init_layer<<<node_blocks, 256>>>(n);
    edge_score<<<ew_blocks, 256>>>(ei, att1, E, etot);
    edge_norm<<<nh_blocks, 256>>>(ei, E, etot);
    edge_aggr<<<ew_blocks, 256>>>(ei, E, etot);
    bias_relu<<<node_blocks, 256>>>(b1, n);

    // ---- layer 2 (act = g_h) ----
    gemm128<<<gemm_blocks, 256>>>(nullptr, Wl2, 1, 0, n);   // -> g_xl
    gemm128<<<gemm_blocks, 256>>>(nullptr, Wr2, 1, 1, n);   // -> g_xr
    init_layer<<<node_blocks, 256>>>(n);
    edge_score<<<ew_blocks, 256>>>(ei, att2, E, etot);
    edge_norm<<<nh_blocks, 256>>>(ei, E, etot);
    edge_aggr<<<ew_blocks, 256>>>(ei, E, etot);
    bias_relu<<<node_blocks, 256>>>(b2, n);

    // ---- fc ----
    fc_out<<<fc_blocks, 256>>>(Wfc, bfc, out, n);
}